// round 5
// baseline (speedup 1.0000x reference)
#include <cuda_runtime.h>
#include <cstdint>

#define NUM_USERS 100000
#define NUM_ITEMS 50000
#define N_NODES   150000
#define EMB       64
#define BATCH     16384
#define NNZ_MAX   2400000
#define NB_SCAN   ((N_NODES + 255) / 256)

// ---------------- scratch (static device allocations; no cudaMalloc) --------
__device__ float g_feat0[N_NODES * EMB];
__device__ float g_feat1[N_NODES * EMB];
__device__ float g_feat2[N_NODES * EMB];
__device__ int   g_cnt[N_NODES];
__device__ int   g_rowptr[N_NODES + 1];
__device__ int   g_cursor[N_NODES];
__device__ int   g_part[NB_SCAN];
__device__ int   g_partscan[NB_SCAN];
__device__ int2  g_edges[NNZ_MAX];          // sorted-by-row (col, val_bits)

// ---------------- kernel: feat0 = concat(uEmb, iEmb) ------------------------
__global__ void init_feat_kernel(const float4* __restrict__ uEmb,
                                 const float4* __restrict__ iEmb) {
    int idx = blockIdx.x * blockDim.x + threadIdx.x;   // over N_NODES*16 float4
    if (idx >= N_NODES * 16) return;
    ((float4*)g_feat0)[idx] =
        (idx < NUM_USERS * 16) ? uEmb[idx] : iEmb[idx - NUM_USERS * 16];
}

// ---------------- CSR build: histogram + scan + scatter ---------------------
__global__ void zero_cnt_kernel() {
    int i = blockIdx.x * 256 + threadIdx.x;
    if (i < N_NODES) g_cnt[i] = 0;
}

__global__ void hist_kernel(const int* __restrict__ rows, int nnz) {
    int e = blockIdx.x * 256 + threadIdx.x;
    if (e < nnz) atomicAdd(&g_cnt[rows[e]], 1);
}

__global__ void scan1_kernel() {
    __shared__ int sm[256];
    int t = threadIdx.x;
    int i = blockIdx.x * 256 + t;
    int c = (i < N_NODES) ? g_cnt[i] : 0;
    sm[t] = c;
    __syncthreads();
    #pragma unroll
    for (int off = 1; off < 256; off <<= 1) {
        int v = (t >= off) ? sm[t - off] : 0;
        __syncthreads();
        sm[t] += v;
        __syncthreads();
    }
    if (i < N_NODES) g_rowptr[i] = sm[t] - c;      // block-local exclusive
    if (t == 255) g_part[blockIdx.x] = sm[255];    // block total
}

__global__ void scan2_kernel() {
    __shared__ int sm[1024];
    int t = threadIdx.x;
    int c = (t < NB_SCAN) ? g_part[t] : 0;
    sm[t] = c;
    __syncthreads();
    #pragma unroll
    for (int off = 1; off < 1024; off <<= 1) {
        int v = (t >= off) ? sm[t - off] : 0;
        __syncthreads();
        sm[t] += v;
        __syncthreads();
    }
    if (t < NB_SCAN) g_partscan[t] = sm[t] - c;    // exclusive
}

__global__ void scan3_kernel(int nnz) {
    int t = threadIdx.x;
    int i = blockIdx.x * 256 + t;
    if (i < N_NODES) {
        int v = g_rowptr[i] + g_partscan[blockIdx.x];
        g_rowptr[i] = v;
        g_cursor[i] = v;
    }
    if (i == 0) g_rowptr[N_NODES] = nnz;
}

__global__ void scatter_kernel(const int*   __restrict__ rows,
                               const int*   __restrict__ cols,
                               const float* __restrict__ vals, int nnz) {
    int e = blockIdx.x * 256 + threadIdx.x;
    if (e >= nnz) return;
    int r = rows[e];
    int pos = atomicAdd(&g_cursor[r], 1);
    g_edges[pos] = make_int2(cols[e], __float_as_int(vals[e]));
}

// ---------------- fused layer: feat_out = relu((L@x + x) @ W + b) -----------
// Pair-lane mapping: lane l owns feature elements (2l, 2l+1) -> each edge
// gather is ONE LDG.64 (32 lanes x 8B = 256B, perfectly coalesced).
// One warp handles 4 consecutive rows, CSR accumulation in float2 registers,
// then shuffle-GEMM epilogue with float4-packed weights in smem.
__global__ __launch_bounds__(256)
void spmm_gemm_kernel(const float2* __restrict__ x,
                      const float*  __restrict__ W,
                      const float*  __restrict__ b,
                      float2* __restrict__ out, int nrows) {
    // sW[kp*32+j] = (W[2kp][2j], W[2kp][2j+1], W[2kp+1][2j], W[2kp+1][2j+1])
    __shared__ float4 sW[32 * 32];
    __shared__ float2 sb[32];
    int tid = threadIdx.x;
    #pragma unroll
    for (int i = tid; i < 1024; i += 256) {
        int kp = i >> 5, j = i & 31;
        sW[i] = make_float4(W[(2 * kp) * 64 + 2 * j], W[(2 * kp) * 64 + 2 * j + 1],
                            W[(2 * kp + 1) * 64 + 2 * j], W[(2 * kp + 1) * 64 + 2 * j + 1]);
    }
    if (tid < 32) sb[tid] = make_float2(b[2 * tid], b[2 * tid + 1]);
    __syncthreads();

    int lane = tid & 31;
    int warp = tid >> 5;
    int r0 = (blockIdx.x * 8 + warp) * 4;

    float2 acc[4];
    #pragma unroll
    for (int rr = 0; rr < 4; rr++) {
        int row = r0 + rr;
        if (row >= nrows) { acc[rr] = make_float2(0.f, 0.f); continue; }
        float2 a = x[(size_t)row * 32 + lane];        // self loop
        int s = g_rowptr[row], e = g_rowptr[row + 1];
        int i = s;
        for (; i + 4 <= e; i += 4) {
            int2 c0 = g_edges[i],     c1 = g_edges[i + 1];
            int2 c2 = g_edges[i + 2], c3 = g_edges[i + 3];
            float2 x0 = x[(size_t)c0.x * 32 + lane];
            float2 x1 = x[(size_t)c1.x * 32 + lane];
            float2 x2 = x[(size_t)c2.x * 32 + lane];
            float2 x3 = x[(size_t)c3.x * 32 + lane];
            float v0 = __int_as_float(c0.y), v1 = __int_as_float(c1.y);
            float v2 = __int_as_float(c2.y), v3 = __int_as_float(c3.y);
            a.x += v0 * x0.x;  a.y += v0 * x0.y;
            a.x += v1 * x1.x;  a.y += v1 * x1.y;
            a.x += v2 * x2.x;  a.y += v2 * x2.y;
            a.x += v3 * x3.x;  a.y += v3 * x3.y;
        }
        for (; i < e; i++) {
            int2 c = g_edges[i];
            float2 xv = x[(size_t)c.x * 32 + lane];
            float v = __int_as_float(c.y);
            a.x += v * xv.x;  a.y += v * xv.y;
        }
        acc[rr] = a;
    }

    // GEMM epilogue: o[2j..2j+1] = relu(b + sum_k h[k] * W[k][2j..2j+1])
    float2 o[4];
    #pragma unroll
    for (int rr = 0; rr < 4; rr++) o[rr] = sb[lane];
    #pragma unroll
    for (int kp = 0; kp < 32; kp++) {
        float4 w = sW[kp * 32 + lane];
        #pragma unroll
        for (int rr = 0; rr < 4; rr++) {
            float h0 = __shfl_sync(0xffffffffu, acc[rr].x, kp);  // h[2kp]
            float h1 = __shfl_sync(0xffffffffu, acc[rr].y, kp);  // h[2kp+1]
            o[rr].x += h0 * w.x + h1 * w.z;
            o[rr].y += h0 * w.y + h1 * w.w;
        }
    }
    #pragma unroll
    for (int rr = 0; rr < 4; rr++) {
        int row = r0 + rr;
        if (row >= nrows) break;
        out[(size_t)row * 32 + lane] =
            make_float2(fmaxf(o[rr].x, 0.f), fmaxf(o[rr].y, 0.f));
    }
}

// ---------------- fused gather + 3-layer MLP --------------------------------
__global__ __launch_bounds__(256)
void mlp_fused_kernel(const int*   __restrict__ userIdx,
                      const int*   __restrict__ itemIdx,
                      const float* __restrict__ W1, const float* __restrict__ b1,
                      const float* __restrict__ W2, const float* __restrict__ b2,
                      const float* __restrict__ W3, const float* __restrict__ b3,
                      float* __restrict__ out) {
    __shared__ float4 sW[32 * 32];    // current W1 segment, packed like spmm_gemm
    __shared__ float  sW2[64 * 32];
    __shared__ float  sb2[32], sW3[32];
    __shared__ float  sb3;

    int tid = threadIdx.x, lane = tid & 31, warp = tid >> 5;
    #pragma unroll
    for (int i = tid; i < 2048; i += 256) sW2[i] = W2[i];
    if (tid < 32) { sb2[tid] = b2[tid]; sW3[tid] = W3[tid]; }
    if (tid == 0) sb3 = b3[0];

    int base = blockIdx.x * 64 + warp * 8;
    int unode[8], inode[8];
    #pragma unroll
    for (int r = 0; r < 8; r++) {
        unode[r] = __ldg(userIdx + base + r);
        inode[r] = __ldg(itemIdx + base + r) + NUM_USERS;
    }

    // acc pair: lane l owns outputs (2l, 2l+1) of the 64-wide m1 row
    float2 bb = make_float2(__ldg(b1 + 2 * lane), __ldg(b1 + 2 * lane + 1));
    float2 acc[8];
    #pragma unroll
    for (int r = 0; r < 8; r++) acc[r] = bb;

    #pragma unroll
    for (int kk = 0; kk < 6; kk++) {
        __syncthreads();
        #pragma unroll
        for (int i = tid; i < 1024; i += 256) {
            int kp = i >> 5, j = i & 31;
            const float* Wseg = W1 + kk * 64 * 64;
            sW[i] = make_float4(Wseg[(2 * kp) * 64 + 2 * j], Wseg[(2 * kp) * 64 + 2 * j + 1],
                                Wseg[(2 * kp + 1) * 64 + 2 * j], Wseg[(2 * kp + 1) * 64 + 2 * j + 1]);
        }
        __syncthreads();

        int seg = (kk < 3) ? kk : kk - 3;
        const float2* src = (const float2*)((seg == 0) ? g_feat0 :
                                            (seg == 1) ? g_feat1 : g_feat2);
        float2 a[8];
        #pragma unroll
        for (int r = 0; r < 8; r++) {
            int node = (kk < 3) ? unode[r] : inode[r];
            a[r] = src[(size_t)node * 32 + lane];
        }
        #pragma unroll
        for (int kp = 0; kp < 32; kp++) {
            float4 w = sW[kp * 32 + lane];
            #pragma unroll
            for (int r = 0; r < 8; r++) {
                float h0 = __shfl_sync(0xffffffffu, a[r].x, kp);
                float h1 = __shfl_sync(0xffffffffu, a[r].y, kp);
                acc[r].x += h0 * w.x + h1 * w.z;
                acc[r].y += h0 * w.y + h1 * w.w;
            }
        }
    }

    // stages 2+3, in-warp. m1[2l]=acc.x, m1[2l+1]=acc.y (lane l).
    #pragma unroll
    for (int r = 0; r < 8; r++) {
        float m0 = fmaxf(acc[r].x, 0.f);
        float m1v = fmaxf(acc[r].y, 0.f);
        float s2 = sb2[lane];                 // lane = output col (0..31)
        #pragma unroll
        for (int kp = 0; kp < 32; kp++) {
            float h0 = __shfl_sync(0xffffffffu, m0, kp);
            float h1 = __shfl_sync(0xffffffffu, m1v, kp);
            s2 += h0 * sW2[(2 * kp) * 32 + lane];
            s2 += h1 * sW2[(2 * kp + 1) * 32 + lane];
        }
        float p = s2 * sW3[lane];             // no ReLU after W2 (matches ref)
        #pragma unroll
        for (int off = 16; off > 0; off >>= 1)
            p += __shfl_xor_sync(0xffffffffu, p, off);
        if (lane == 0) out[base + r] = p + sb3;
    }
}

// ---------------- launch ----------------------------------------------------
extern "C" void kernel_launch(void* const* d_in, const int* in_sizes, int n_in,
                              void* d_out, int out_size) {
    const int*   userIdx = (const int*)  d_in[0];
    const int*   itemIdx = (const int*)  d_in[1];
    const int*   lapRows = (const int*)  d_in[2];
    const int*   lapCols = (const int*)  d_in[3];
    const float* lapVals = (const float*)d_in[4];
    const float* uEmb    = (const float*)d_in[5];
    const float* iEmb    = (const float*)d_in[6];
    const float* gW0     = (const float*)d_in[7];
    const float* gb0     = (const float*)d_in[8];
    const float* gW1     = (const float*)d_in[9];
    const float* gb1     = (const float*)d_in[10];
    const float* W1      = (const float*)d_in[11];
    const float* b1      = (const float*)d_in[12];
    const float* W2      = (const float*)d_in[13];
    const float* b2      = (const float*)d_in[14];
    const float* W3      = (const float*)d_in[15];
    const float* b3      = (const float*)d_in[16];
    float* out = (float*)d_out;

    const int nnz = in_sizes[2];

    float *feat0, *feat1, *feat2;
    cudaGetSymbolAddress((void**)&feat0, g_feat0);
    cudaGetSymbolAddress((void**)&feat1, g_feat1);
    cudaGetSymbolAddress((void**)&feat2, g_feat2);

    // 1. feat0 = concat(uEmb, iEmb)
    init_feat_kernel<<<(N_NODES * 16 + 255) / 256, 256>>>((const float4*)uEmb,
                                                          (const float4*)iEmb);

    // 2. build CSR (histogram -> scan -> scatter); reused by both layers
    const int eb = (nnz + 255) / 256;
    zero_cnt_kernel<<<NB_SCAN, 256>>>();
    hist_kernel<<<eb, 256>>>(lapRows, nnz);
    scan1_kernel<<<NB_SCAN, 256>>>();
    scan2_kernel<<<1, 1024>>>();
    scan3_kernel<<<NB_SCAN, 256>>>(nnz);
    scatter_kernel<<<eb, 256>>>(lapRows, lapCols, lapVals, nnz);

    // 3. fused layers: feat_{k+1} = relu((L @ feat_k + feat_k) @ W + b)
    const int lb = (N_NODES + 31) / 32;   // 8 warps x 4 rows per block
    spmm_gemm_kernel<<<lb, 256>>>((const float2*)feat0, gW0, gb0,
                                  (float2*)feat1, N_NODES);
    spmm_gemm_kernel<<<lb, 256>>>((const float2*)feat1, gW1, gb1,
                                  (float2*)feat2, N_NODES);

    // 4. fused gather + 3-layer MLP
    mlp_fused_kernel<<<BATCH / 64, 256>>>(userIdx, itemIdx,
                                          W1, b1, W2, b2, W3, b3, out);
}

// round 6
// speedup vs baseline: 1.0937x; 1.0937x over previous
#include <cuda_runtime.h>
#include <cstdint>

#define NUM_USERS 100000
#define NUM_ITEMS 50000
#define N_NODES   150000
#define EMB       64
#define BATCH     16384
#define NNZ_MAX   2400000
#define NB_SCAN   ((N_NODES + 255) / 256)
#define ROWS_PER_BLOCK 32
#define EDGE_CAP  1280          // int2 staging cap per block (10 KB smem)

// ---------------- scratch (static device allocations; no cudaMalloc) --------
__device__ float g_feat0[N_NODES * EMB];
__device__ float g_feat1[N_NODES * EMB];
__device__ float g_feat2[N_NODES * EMB];
__device__ int   g_cnt[N_NODES];
__device__ int   g_rowptr[N_NODES + 1];
__device__ int   g_cursor[N_NODES];
__device__ int   g_part[NB_SCAN];
__device__ int   g_partscan[NB_SCAN];
__device__ int2  g_edges[NNZ_MAX];          // sorted-by-row (col, val_bits)

// ---------------- kernel: feat0 = concat(uEmb, iEmb) ------------------------
__global__ void init_feat_kernel(const float4* __restrict__ uEmb,
                                 const float4* __restrict__ iEmb) {
    int idx = blockIdx.x * blockDim.x + threadIdx.x;   // over N_NODES*16 float4
    if (idx >= N_NODES * 16) return;
    ((float4*)g_feat0)[idx] =
        (idx < NUM_USERS * 16) ? uEmb[idx] : iEmb[idx - NUM_USERS * 16];
}

// ---------------- CSR build: histogram + scan + scatter ---------------------
__global__ void zero_cnt_kernel() {
    int i = blockIdx.x * 256 + threadIdx.x;
    if (i < N_NODES) g_cnt[i] = 0;
}

__global__ void hist_kernel(const int* __restrict__ rows, int nnz) {
    int e = blockIdx.x * 256 + threadIdx.x;
    if (e < nnz) atomicAdd(&g_cnt[rows[e]], 1);
}

__global__ void scan1_kernel() {
    __shared__ int sm[256];
    int t = threadIdx.x;
    int i = blockIdx.x * 256 + t;
    int c = (i < N_NODES) ? g_cnt[i] : 0;
    sm[t] = c;
    __syncthreads();
    #pragma unroll
    for (int off = 1; off < 256; off <<= 1) {
        int v = (t >= off) ? sm[t - off] : 0;
        __syncthreads();
        sm[t] += v;
        __syncthreads();
    }
    if (i < N_NODES) g_rowptr[i] = sm[t] - c;      // block-local exclusive
    if (t == 255) g_part[blockIdx.x] = sm[255];    // block total
}

__global__ void scan2_kernel() {
    __shared__ int sm[1024];
    int t = threadIdx.x;
    int c = (t < NB_SCAN) ? g_part[t] : 0;
    sm[t] = c;
    __syncthreads();
    #pragma unroll
    for (int off = 1; off < 1024; off <<= 1) {
        int v = (t >= off) ? sm[t - off] : 0;
        __syncthreads();
        sm[t] += v;
        __syncthreads();
    }
    if (t < NB_SCAN) g_partscan[t] = sm[t] - c;    // exclusive
}

__global__ void scan3_kernel(int nnz) {
    int t = threadIdx.x;
    int i = blockIdx.x * 256 + t;
    if (i < N_NODES) {
        int v = g_rowptr[i] + g_partscan[blockIdx.x];
        g_rowptr[i] = v;
        g_cursor[i] = v;
    }
    if (i == 0) g_rowptr[N_NODES] = nnz;
}

__global__ void scatter_kernel(const int*   __restrict__ rows,
                               const int*   __restrict__ cols,
                               const float* __restrict__ vals, int nnz) {
    int e = blockIdx.x * 256 + threadIdx.x;
    if (e >= nnz) return;
    int r = rows[e];
    int pos = atomicAdd(&g_cursor[r], 1);
    g_edges[pos] = make_int2(cols[e], __float_as_int(vals[e]));
}

// ---------------- fused layer: feat_out = relu((L@x + x) @ W + b) -----------
// Block owns 32 consecutive rows; the block's contiguous CSR edge segment is
// staged into smem with ONE coalesced sweep, so per-edge metadata comes from
// LDS (29 cyc broadcast) instead of a serial L2 load ahead of every gather.
// One warp = 4 rows; register accumulation; shuffle-GEMM epilogue.
__global__ __launch_bounds__(256)
void spmm_gemm_kernel(const float* __restrict__ x,
                      const float* __restrict__ W,
                      const float* __restrict__ b,
                      float* __restrict__ out, int nrows) {
    __shared__ float2 sW[64 * 32];    // sW[k*32+j] = (W[k][j], W[k][j+32])
    __shared__ float  sb[64];
    __shared__ int2   sE[EDGE_CAP];
    int tid = threadIdx.x;
    #pragma unroll
    for (int i = tid; i < 2048; i += 256) {
        int k = i >> 5, j = i & 31;
        sW[i] = make_float2(W[k * 64 + j], W[k * 64 + j + 32]);
    }
    if (tid < 64) sb[tid] = b[tid];

    int r_base = blockIdx.x * ROWS_PER_BLOCK;
    int r_end  = min(r_base + ROWS_PER_BLOCK, nrows);
    int blk_s  = g_rowptr[r_base];
    int blk_e  = g_rowptr[r_end];
    int cnt    = blk_e - blk_s;
    int stage  = min(cnt, EDGE_CAP);
    for (int i = tid; i < stage; i += 256) sE[i] = g_edges[blk_s + i];
    __syncthreads();

    int lane = tid & 31;
    int warp = tid >> 5;
    int r0 = r_base + warp * 4;

    float acc0[4], acc1[4];
    #pragma unroll
    for (int rr = 0; rr < 4; rr++) {
        int row = r0 + rr;
        if (row >= nrows) { acc0[rr] = 0.f; acc1[rr] = 0.f; continue; }
        const float* xr = x + (size_t)row * 64;
        float a0 = xr[lane], a1 = xr[lane + 32];           // self loop
        int s = g_rowptr[row] - blk_s, e = g_rowptr[row + 1] - blk_s;
        int i = s;
        for (; i + 4 <= e; i += 4) {
            int2 c0 = (i     < EDGE_CAP) ? sE[i]     : g_edges[blk_s + i];
            int2 c1 = (i + 1 < EDGE_CAP) ? sE[i + 1] : g_edges[blk_s + i + 1];
            int2 c2 = (i + 2 < EDGE_CAP) ? sE[i + 2] : g_edges[blk_s + i + 2];
            int2 c3 = (i + 3 < EDGE_CAP) ? sE[i + 3] : g_edges[blk_s + i + 3];
            float x00 = x[(size_t)c0.x * 64 + lane], x01 = x[(size_t)c0.x * 64 + lane + 32];
            float x10 = x[(size_t)c1.x * 64 + lane], x11 = x[(size_t)c1.x * 64 + lane + 32];
            float x20 = x[(size_t)c2.x * 64 + lane], x21 = x[(size_t)c2.x * 64 + lane + 32];
            float x30 = x[(size_t)c3.x * 64 + lane], x31 = x[(size_t)c3.x * 64 + lane + 32];
            a0 += __int_as_float(c0.y) * x00;  a1 += __int_as_float(c0.y) * x01;
            a0 += __int_as_float(c1.y) * x10;  a1 += __int_as_float(c1.y) * x11;
            a0 += __int_as_float(c2.y) * x20;  a1 += __int_as_float(c2.y) * x21;
            a0 += __int_as_float(c3.y) * x30;  a1 += __int_as_float(c3.y) * x31;
        }
        for (; i < e; i++) {
            int2 c = (i < EDGE_CAP) ? sE[i] : g_edges[blk_s + i];
            a0 += __int_as_float(c.y) * x[(size_t)c.x * 64 + lane];
            a1 += __int_as_float(c.y) * x[(size_t)c.x * 64 + lane + 32];
        }
        acc0[rr] = a0; acc1[rr] = a1;
    }

    // GEMM epilogue: out[c] = relu(b[c] + sum_k h[k] * W[k][c])
    float o0[4], o1[4];
    #pragma unroll
    for (int rr = 0; rr < 4; rr++) { o0[rr] = sb[lane]; o1[rr] = sb[lane + 32]; }
    #pragma unroll
    for (int k = 0; k < 32; k++) {
        float2 w = sW[k * 32 + lane];
        #pragma unroll
        for (int rr = 0; rr < 4; rr++) {
            float hk = __shfl_sync(0xffffffffu, acc0[rr], k);
            o0[rr] += hk * w.x;  o1[rr] += hk * w.y;
        }
    }
    #pragma unroll
    for (int k = 0; k < 32; k++) {
        float2 w = sW[(k + 32) * 32 + lane];
        #pragma unroll
        for (int rr = 0; rr < 4; rr++) {
            float hk = __shfl_sync(0xffffffffu, acc1[rr], k);
            o0[rr] += hk * w.x;  o1[rr] += hk * w.y;
        }
    }
    #pragma unroll
    for (int rr = 0; rr < 4; rr++) {
        int row = r0 + rr;
        if (row >= nrows) break;
        float* op = out + (size_t)row * 64;
        op[lane]      = fmaxf(o0[rr], 0.f);
        op[lane + 32] = fmaxf(o1[rr], 0.f);
    }
}

// ---------------- fused gather + 3-layer MLP (round-4 proven version) -------
__global__ __launch_bounds__(256)
void mlp_fused_kernel(const int*   __restrict__ userIdx,
                      const int*   __restrict__ itemIdx,
                      const float* __restrict__ W1, const float* __restrict__ b1,
                      const float* __restrict__ W2, const float* __restrict__ b2,
                      const float* __restrict__ W3, const float* __restrict__ b3,
                      float* __restrict__ out) {
    __shared__ float2 sW[64 * 32];    // current W1 segment, paired cols
    __shared__ float  sW2[64 * 32];
    __shared__ float  sb2[32], sW3[32];
    __shared__ float  sb3;

    int tid = threadIdx.x, lane = tid & 31, warp = tid >> 5;
    #pragma unroll
    for (int i = tid; i < 2048; i += 256) sW2[i] = W2[i];
    if (tid < 32) { sb2[tid] = b2[tid]; sW3[tid] = W3[tid]; }
    if (tid == 0) sb3 = b3[0];

    int base = blockIdx.x * 64 + warp * 8;
    int unode[8], inode[8];
    #pragma unroll
    for (int r = 0; r < 8; r++) {
        unode[r] = __ldg(userIdx + base + r);
        inode[r] = __ldg(itemIdx + base + r) + NUM_USERS;
    }

    float bb0 = __ldg(b1 + lane), bb1 = __ldg(b1 + lane + 32);
    float acc0[8], acc1[8];
    #pragma unroll
    for (int r = 0; r < 8; r++) { acc0[r] = bb0; acc1[r] = bb1; }

    #pragma unroll
    for (int kk = 0; kk < 6; kk++) {
        __syncthreads();
        #pragma unroll
        for (int i = tid; i < 2048; i += 256) {
            int k = i >> 5, j = i & 31;
            sW[i] = make_float2(W1[(kk * 64 + k) * 64 + j],
                                W1[(kk * 64 + k) * 64 + j + 32]);
        }
        __syncthreads();

        int seg = (kk < 3) ? kk : kk - 3;
        const float* src = (seg == 0) ? g_feat0 : (seg == 1) ? g_feat1 : g_feat2;

        float a0[8], a1[8];
        #pragma unroll
        for (int r = 0; r < 8; r++) {
            int node = (kk < 3) ? unode[r] : inode[r];
            const float* er = src + (size_t)node * 64;
            a0[r] = er[lane]; a1[r] = er[lane + 32];
        }
        #pragma unroll
        for (int k = 0; k < 32; k++) {
            float2 w = sW[k * 32 + lane];
            #pragma unroll
            for (int r = 0; r < 8; r++) {
                float hk = __shfl_sync(0xffffffffu, a0[r], k);
                acc0[r] += hk * w.x;  acc1[r] += hk * w.y;
            }
        }
        #pragma unroll
        for (int k = 0; k < 32; k++) {
            float2 w = sW[(k + 32) * 32 + lane];
            #pragma unroll
            for (int r = 0; r < 8; r++) {
                float hk = __shfl_sync(0xffffffffu, a1[r], k);
                acc0[r] += hk * w.x;  acc1[r] += hk * w.y;
            }
        }
    }

    // stages 2+3, in-warp
    #pragma unroll
    for (int r = 0; r < 8; r++) {
        float m0  = fmaxf(acc0[r], 0.f);
        float m1v = fmaxf(acc1[r], 0.f);
        float acc = sb2[lane];                 // lane = output col (0..31)
        #pragma unroll
        for (int k = 0; k < 32; k++) {
            float hk = __shfl_sync(0xffffffffu, m0, k);
            acc += hk * sW2[k * 32 + lane];
        }
        #pragma unroll
        for (int k = 0; k < 32; k++) {
            float hk = __shfl_sync(0xffffffffu, m1v, k);
            acc += hk * sW2[(k + 32) * 32 + lane];
        }
        float p = acc * sW3[lane];             // no ReLU after W2 (matches ref)
        #pragma unroll
        for (int off = 16; off > 0; off >>= 1)
            p += __shfl_xor_sync(0xffffffffu, p, off);
        if (lane == 0) out[base + r] = p + sb3;
    }
}

// ---------------- launch ----------------------------------------------------
extern "C" void kernel_launch(void* const* d_in, const int* in_sizes, int n_in,
                              void* d_out, int out_size) {
    const int*   userIdx = (const int*)  d_in[0];
    const int*   itemIdx = (const int*)  d_in[1];
    const int*   lapRows = (const int*)  d_in[2];
    const int*   lapCols = (const int*)  d_in[3];
    const float* lapVals = (const float*)d_in[4];
    const float* uEmb    = (const float*)d_in[5];
    const float* iEmb    = (const float*)d_in[6];
    const float* gW0     = (const float*)d_in[7];
    const float* gb0     = (const float*)d_in[8];
    const float* gW1     = (const float*)d_in[9];
    const float* gb1     = (const float*)d_in[10];
    const float* W1      = (const float*)d_in[11];
    const float* b1      = (const float*)d_in[12];
    const float* W2      = (const float*)d_in[13];
    const float* b2      = (const float*)d_in[14];
    const float* W3      = (const float*)d_in[15];
    const float* b3      = (const float*)d_in[16];
    float* out = (float*)d_out;

    const int nnz = in_sizes[2];

    float *feat0, *feat1, *feat2;
    cudaGetSymbolAddress((void**)&feat0, g_feat0);
    cudaGetSymbolAddress((void**)&feat1, g_feat1);
    cudaGetSymbolAddress((void**)&feat2, g_feat2);

    // 1. feat0 = concat(uEmb, iEmb)
    init_feat_kernel<<<(N_NODES * 16 + 255) / 256, 256>>>((const float4*)uEmb,
                                                          (const float4*)iEmb);

    // 2. build CSR (histogram -> scan -> scatter); reused by both layers
    const int eb = (nnz + 255) / 256;
    zero_cnt_kernel<<<NB_SCAN, 256>>>();
    hist_kernel<<<eb, 256>>>(lapRows, nnz);
    scan1_kernel<<<NB_SCAN, 256>>>();
    scan2_kernel<<<1, 1024>>>();
    scan3_kernel<<<NB_SCAN, 256>>>(nnz);
    scatter_kernel<<<eb, 256>>>(lapRows, lapCols, lapVals, nnz);

    // 3. fused layers: feat_{k+1} = relu((L @ feat_k + feat_k) @ W + b)
    const int lb = (N_NODES + ROWS_PER_BLOCK - 1) / ROWS_PER_BLOCK;
    spmm_gemm_kernel<<<lb, 256>>>(feat0, gW0, gb0, feat1, N_NODES);
    spmm_gemm_kernel<<<lb, 256>>>(feat1, gW1, gb1, feat2, N_NODES);

    // 4. fused gather + 3-layer MLP
    mlp_fused_kernel<<<BATCH / 64, 256>>>(userIdx, itemIdx,
                                          W1, b1, W2, b2, W3, b3, out);
}